// round 16
// baseline (speedup 1.0000x reference)
#include <cuda_runtime.h>
#include <cuda_fp16.h>

#define N_NODES 100000
#define N_EDGES 1600000
#define D_IN    256
#define HF      128     // N_HEADS * D_OUT
#define NEG_SLOPE 0.2f

#define SCAN_BLK 256
#define N_SCAN_BLOCKS ((N_NODES + SCAN_BLK - 1) / SCAN_BLK)   // 391

#define GEMM_BM 128
#define GEMM_GRID ((N_NODES + GEMM_BM - 1) / GEMM_BM)         // 782

// ---------------- scratch (device globals: allocation-free) ----------------
__device__ __half g_ft2[(size_t)N_NODES * HF];       // 25.6 MB fp16 features
__device__ __half g_wh[HF * D_IN];                   // W fp16, [c][k]
__device__ float  g_elf[N_NODES * 4];
__device__ float  g_erf[N_NODES * 4];
__device__ int    g_counts[N_NODES];
__device__ int    g_offsets[N_NODES];
__device__ unsigned long long g_scan_state[N_SCAN_BLOCKS];  // flag<<32 | value
__device__ int    g_rank[N_EDGES];                   // edge rank within its dst
__device__ int    g_src_sorted[N_EDGES + 8];         // +pad: pipeline overrun safe

// ---------------- 0. zero counters + scan state ----------------
__global__ void zero_kernel() {
    int i = blockIdx.x * blockDim.x + threadIdx.x;
    if (i < N_NODES) g_counts[i] = 0;
    if (i < N_SCAN_BLOCKS) g_scan_state[i] = 0ULL;
}

// ---------------- 1. W fp32 -> fp16 ----------------
__global__ void wtrans_kernel(const float* __restrict__ w) {
    int i = blockIdx.x * blockDim.x + threadIdx.x;
    if (i < HF * D_IN) g_wh[i] = __float2half(w[i]);
}

// ---------------- 2. HMMA GEMM + fused el/er epilogue ----------------
// Block 128x128xK256, 8 warps (4m x 2n), warp tile 32x64 = 2x8 m16n8k16.
__global__ void __launch_bounds__(256) gemm_kernel(const float* __restrict__ x,
                                                   const float* __restrict__ al,
                                                   const float* __restrict__ ar) {
    extern __shared__ char smem[];
    char* As = smem;            // 65536 bytes
    char* Bs = smem + 65536;    // 65536 bytes

    int tid  = threadIdx.x;
    int lane = tid & 31;
    int wid  = tid >> 5;
    int wm   = wid & 3;
    int wn   = wid >> 2;
    int row0 = blockIdx.x * GEMM_BM;

#pragma unroll
    for (int it = 0; it < 16; it++) {
        int cid = tid + 256 * it;
        int row = cid >> 5;
        int ck  = cid & 31;
        int grow = row0 + row;
        float4 f0, f1;
        if (grow < N_NODES) {
            const float4* xp = (const float4*)(x + (size_t)grow * D_IN + ck * 8);
            f0 = __ldg(xp); f1 = __ldg(xp + 1);
        } else {
            f0 = make_float4(0.f, 0.f, 0.f, 0.f); f1 = f0;
        }
        __half2 h0 = __floats2half2_rn(f0.x, f0.y);
        __half2 h1 = __floats2half2_rn(f0.z, f0.w);
        __half2 h2 = __floats2half2_rn(f1.x, f1.y);
        __half2 h3 = __floats2half2_rn(f1.z, f1.w);
        uint4 v = make_uint4(*(unsigned*)&h0, *(unsigned*)&h1,
                             *(unsigned*)&h2, *(unsigned*)&h3);
        *(uint4*)(As + row * 512 + ((ck ^ (row & 7)) << 4)) = v;
    }
#pragma unroll
    for (int it = 0; it < 16; it++) {
        int cid = tid + 256 * it;
        int row = cid >> 5;
        int ck  = cid & 31;
        uint4 v = __ldg((const uint4*)(g_wh + row * D_IN + ck * 8));
        *(uint4*)(Bs + row * 512 + ((ck ^ (row & 7)) << 4)) = v;
    }
    __syncthreads();

    unsigned aBase = (unsigned)__cvta_generic_to_shared(As);
    unsigned bBase = (unsigned)__cvta_generic_to_shared(Bs);

    float c[2][8][4];
#pragma unroll
    for (int mt = 0; mt < 2; mt++)
#pragma unroll
        for (int nt = 0; nt < 8; nt++)
#pragma unroll
            for (int e = 0; e < 4; e++) c[mt][nt][e] = 0.f;

    int aRowL = wm * 32 + (lane & 7) + ((lane >> 3) & 1) * 8;
    int aKbL  = (lane >> 4) * 16;
    int bRowL = wn * 64 + (lane & 7) + (lane >> 4) * 8;
    int bKbL  = ((lane >> 3) & 1) * 16;

#pragma unroll
    for (int ks = 0; ks < 16; ks++) {
        int kb = ks * 32;
        unsigned a[2][4];
#pragma unroll
        for (int mt = 0; mt < 2; mt++) {
            int r = aRowL + mt * 16;
            int kbyte = kb + aKbL;
            unsigned addr = aBase + r * 512 + ((((kbyte >> 4) ^ (r & 7)) << 4));
            asm volatile(
                "ldmatrix.sync.aligned.m8n8.x4.shared.b16 {%0,%1,%2,%3}, [%4];"
                : "=r"(a[mt][0]), "=r"(a[mt][1]), "=r"(a[mt][2]), "=r"(a[mt][3])
                : "r"(addr));
        }
        unsigned b[8][2];
#pragma unroll
        for (int nt2 = 0; nt2 < 4; nt2++) {
            int r = bRowL + nt2 * 16;
            int kbyte = kb + bKbL;
            unsigned addr = bBase + r * 512 + ((((kbyte >> 4) ^ (r & 7)) << 4));
            unsigned r0, r1, r2, r3;
            asm volatile(
                "ldmatrix.sync.aligned.m8n8.x4.shared.b16 {%0,%1,%2,%3}, [%4];"
                : "=r"(r0), "=r"(r1), "=r"(r2), "=r"(r3)
                : "r"(addr));
            b[nt2 * 2 + 0][0] = r0; b[nt2 * 2 + 0][1] = r1;
            b[nt2 * 2 + 1][0] = r2; b[nt2 * 2 + 1][1] = r3;
        }
#pragma unroll
        for (int mt = 0; mt < 2; mt++)
#pragma unroll
            for (int nt = 0; nt < 8; nt++) {
                asm volatile(
                    "mma.sync.aligned.m16n8k16.row.col.f32.f16.f16.f32 "
                    "{%0,%1,%2,%3}, {%4,%5,%6,%7}, {%8,%9}, {%0,%1,%2,%3};"
                    : "+f"(c[mt][nt][0]), "+f"(c[mt][nt][1]),
                      "+f"(c[mt][nt][2]), "+f"(c[mt][nt][3])
                    : "r"(a[mt][0]), "r"(a[mt][1]), "r"(a[mt][2]), "r"(a[mt][3]),
                      "r"(b[nt][0]), "r"(b[nt][1]));
            }
    }

    int gid = lane >> 2, tig = lane & 3;

    float2 al2[8], ar2[8];
#pragma unroll
    for (int nt = 0; nt < 8; nt++) {
        int col = wn * 64 + nt * 8 + tig * 2;
        al2[nt] = __ldg((const float2*)al + (col >> 1));
        ar2[nt] = __ldg((const float2*)ar + (col >> 1));
    }

#pragma unroll
    for (int mt = 0; mt < 2; mt++) {
        int r0 = row0 + wm * 32 + mt * 16 + gid;
        int r1 = r0 + 8;
        float elA0 = 0.f, elB0 = 0.f, erA0 = 0.f, erB0 = 0.f;
        float elA1 = 0.f, elB1 = 0.f, erA1 = 0.f, erB1 = 0.f;
#pragma unroll
        for (int nt = 0; nt < 8; nt++) {
            int col = wn * 64 + nt * 8 + tig * 2;
            if (r0 < N_NODES) {
                __half2 h = __floats2half2_rn(c[mt][nt][0], c[mt][nt][1]);
                *(__half2*)(g_ft2 + (size_t)r0 * HF + col) = h;
            }
            if (r1 < N_NODES) {
                __half2 h = __floats2half2_rn(c[mt][nt][2], c[mt][nt][3]);
                *(__half2*)(g_ft2 + (size_t)r1 * HF + col) = h;
            }
            float l0 = c[mt][nt][0] * al2[nt].x + c[mt][nt][1] * al2[nt].y;
            float l1 = c[mt][nt][2] * al2[nt].x + c[mt][nt][3] * al2[nt].y;
            float q0 = c[mt][nt][0] * ar2[nt].x + c[mt][nt][1] * ar2[nt].y;
            float q1 = c[mt][nt][2] * ar2[nt].x + c[mt][nt][3] * ar2[nt].y;
            if (nt < 4) { elA0 += l0; elA1 += l1; erA0 += q0; erA1 += q1; }
            else        { elB0 += l0; elB1 += l1; erB0 += q0; erB1 += q1; }
        }
#pragma unroll
        for (int o = 1; o <= 2; o <<= 1) {
            elA0 += __shfl_xor_sync(0xffffffffu, elA0, o);
            elB0 += __shfl_xor_sync(0xffffffffu, elB0, o);
            erA0 += __shfl_xor_sync(0xffffffffu, erA0, o);
            erB0 += __shfl_xor_sync(0xffffffffu, erB0, o);
            elA1 += __shfl_xor_sync(0xffffffffu, elA1, o);
            elB1 += __shfl_xor_sync(0xffffffffu, elB1, o);
            erA1 += __shfl_xor_sync(0xffffffffu, erA1, o);
            erB1 += __shfl_xor_sync(0xffffffffu, erB1, o);
        }
        if (tig == 0) {
            int hA = wn * 2, hB = wn * 2 + 1;
            if (r0 < N_NODES) {
                g_elf[r0 * 4 + hA] = elA0;  g_elf[r0 * 4 + hB] = elB0;
                g_erf[r0 * 4 + hA] = erA0;  g_erf[r0 * 4 + hB] = erB0;
            }
            if (r1 < N_NODES) {
                g_elf[r1 * 4 + hA] = elA1;  g_elf[r1 * 4 + hB] = elB1;
                g_erf[r1 * 4 + hA] = erA1;  g_erf[r1 * 4 + hB] = erB1;
            }
        }
    }
}

// ---------------- 3. histogram of dst + per-edge rank (4 edges/thread) ------
__global__ void hist_kernel(const int* __restrict__ dst) {
    int i = blockIdx.x * blockDim.x + threadIdx.x;
    if (i < N_EDGES / 4) {
        int4 d = __ldg((const int4*)dst + i);
        int4 r;
        r.x = atomicAdd(&g_counts[d.x], 1);
        r.y = atomicAdd(&g_counts[d.y], 1);
        r.z = atomicAdd(&g_counts[d.z], 1);
        r.w = atomicAdd(&g_counts[d.w], 1);
        ((int4*)g_rank)[i] = r;
    }
}

// ---------------- 4. single-pass exclusive scan (decoupled lookback) --------
__global__ void __launch_bounds__(SCAN_BLK) scan_kernel() {
    __shared__ int warp_sums[8];
    __shared__ int s_prefix;
    int t = threadIdx.x, b = blockIdx.x;
    int i = b * SCAN_BLK + t;
    int lane = t & 31, w = t >> 5;

    int v = (i < N_NODES) ? g_counts[i] : 0;
    int xi = v;
#pragma unroll
    for (int o = 1; o < 32; o <<= 1) {
        int u = __shfl_up_sync(0xffffffffu, xi, o);
        if (lane >= o) xi += u;
    }
    if (lane == 31) warp_sums[w] = xi;
    __syncthreads();
    if (w == 0) {
        int s = (lane < 8) ? warp_sums[lane] : 0;
#pragma unroll
        for (int o = 1; o < 8; o <<= 1) {
            int u = __shfl_up_sync(0xffffffffu, s, o);
            if (lane >= o) s += u;
        }
        if (lane < 8) warp_sums[lane] = s;
    }
    __syncthreads();
    int excl = xi - v + ((w > 0) ? warp_sums[w - 1] : 0);
    int block_total = warp_sums[7];

    if (t == 0) {
        if (b == 0) {
            atomicExch(&g_scan_state[0],
                       (2ULL << 32) | (unsigned)block_total);
            s_prefix = 0;
        } else {
            atomicExch(&g_scan_state[b],
                       (1ULL << 32) | (unsigned)block_total);
            int running = 0;
            int p = b - 1;
            while (true) {
                unsigned long long st = atomicAdd(&g_scan_state[p], 0ULL);
                unsigned f = (unsigned)(st >> 32);
                if (f == 2u) { running += (int)(unsigned)st; break; }
                if (f == 1u) { running += (int)(unsigned)st; p--; }
            }
            atomicExch(&g_scan_state[b],
                       (2ULL << 32) | (unsigned)(block_total + running));
            s_prefix = running;
        }
    }
    __syncthreads();
    if (i < N_NODES) g_offsets[i] = excl + s_prefix;
}

// ---------------- 5. scatter src into dst-sorted order (4 edges/thread) -----
__global__ void scatter_kernel(const int* __restrict__ src,
                               const int* __restrict__ dst) {
    int i = blockIdx.x * blockDim.x + threadIdx.x;
    if (i >= N_EDGES / 4) return;
    int4 s = __ldg((const int4*)src + i);
    int4 d = __ldg((const int4*)dst + i);
    int4 r = ((const int4*)g_rank)[i];
    g_src_sorted[g_offsets[d.x] + r.x] = s.x;
    g_src_sorted[g_offsets[d.y] + r.y] = s.y;
    g_src_sorted[g_offsets[d.z] + r.z] = s.z;
    g_src_sorted[g_offsets[d.w] + r.w] = s.w;
}

// ---------------- 6. aggregate: warp/node, half-warp/edge, deep pipeline ----
// Pipeline: (e,v) consumed this iter were loaded LAST iter; src indices run
// two pairs ahead. All speculative indices land in valid/zero-padded memory;
// results masked by w=0.
__global__ void __launch_bounds__(256) agg_kernel(float* __restrict__ out) {
    int n    = (blockIdx.x * blockDim.x + threadIdx.x) >> 5;
    int lane = threadIdx.x & 31;
    if (n >= N_NODES) return;
    int q    = lane & 15;
    int hq   = q >> 2;
    int half = lane >> 4;

    int base = __ldg(&g_offsets[n]);
    int deg  = __ldg(&g_counts[n]);
    float erh = __ldg(&g_erf[n * 4 + hq]);

    const uint4* ft16 = (const uint4*)g_ft2;   // 16 chunks per 256B row
    const float* elf  = g_elf;

    float a[8];
#pragma unroll
    for (int k = 0; k < 8; k++) a[k] = 0.f;
    float d = 0.f;

    // src pipeline (pairs j and j+1); all reads padded-safe
    int s0 = __ldg(&g_src_sorted[base]);
    int s1 = __ldg(&g_src_sorted[base + 1]);
    int s2 = __ldg(&g_src_sorted[base + 2]);
    int s3 = __ldg(&g_src_sorted[base + 3]);

    // (e,v) preload for pair 0
    int   sCur = half ? s1 : s0;
    float e_cur = __ldg(elf + sCur * 4 + hq);
    uint4 v_cur = __ldg(&ft16[(size_t)sCur * 16 + q]);

    for (int j = 0; j < deg; j += 2) {
        bool valid = half ? (j + 1 < deg) : true;
        bool has_next = (j + 2 < deg);

        // issue next pair's dependent loads (independent of this iter's math)
        int   sNxt = half ? s3 : s2;
        float e_nxt = 0.f; uint4 v_nxt = v_cur;
        if (has_next) {
            e_nxt = __ldg(elf + sNxt * 4 + hq);
            v_nxt = __ldg(&ft16[(size_t)sNxt * 16 + q]);
        }
        // prefetch src for pair j+2
        int jn = j + 4;
        int s2n = 0, s3n = 0;
        if (jn < deg) {
            s2n = __ldg(&g_src_sorted[base + jn]);
            s3n = __ldg(&g_src_sorted[base + jn + 1]);
        }

        // consume current pair
        float t = e_cur + erh; t = (t > 0.f) ? t : NEG_SLOPE * t;
        float w = valid ? __expf(t) : 0.f;
        d += w;
        const __half2* hv = (const __half2*)&v_cur;
#pragma unroll
        for (int k = 0; k < 4; k++) {
            float2 f = __half22float2(hv[k]);
            a[2 * k]     += w * f.x;
            a[2 * k + 1] += w * f.y;
        }

        // rotate pipeline
        s2 = s2n; s3 = s3n;
        e_cur = e_nxt; v_cur = v_nxt;
    }

    // combine the two halves
    d += __shfl_xor_sync(0xffffffffu, d, 16);
#pragma unroll
    for (int k = 0; k < 8; k++) a[k] += __shfl_xor_sync(0xffffffffu, a[k], 16);

    float inv = (deg > 0) ? 1.f / d : 0.f;
    if (lane < 16) {
        float4 o0 = make_float4(a[0] * inv, a[1] * inv, a[2] * inv, a[3] * inv);
        float4 o1 = make_float4(a[4] * inv, a[5] * inv, a[6] * inv, a[7] * inv);
        float4* op = (float4*)out + (size_t)n * 32 + q * 2;
        op[0] = o0;
        op[1] = o1;
    }
}

// ---------------- launch: edge-sort chain fully parallel with GEMM ----------
extern "C" void kernel_launch(void* const* d_in, const int* in_sizes, int n_in,
                              void* d_out, int out_size) {
    const float* x    = (const float*)d_in[0];
    const float* fc_w = (const float*)d_in[1];
    const float* al   = (const float*)d_in[2];
    const float* ar   = (const float*)d_in[3];
    const int*   src  = (const int*)d_in[4];
    const int*   dst  = (const int*)d_in[5];
    float*       out  = (float*)d_out;

    static cudaStream_t s2 = nullptr;
    static cudaEvent_t  evF = nullptr, evJ = nullptr;
    if (!s2) {   // first call is the (non-captured) correctness run
        cudaStreamCreateWithFlags(&s2, cudaStreamNonBlocking);
        cudaEventCreateWithFlags(&evF, cudaEventDisableTiming);
        cudaEventCreateWithFlags(&evJ, cudaEventDisableTiming);
        cudaFuncSetAttribute(gemm_kernel,
                             cudaFuncAttributeMaxDynamicSharedMemorySize, 131072);
    }

    // fork
    cudaEventRecord(evF, 0);
    cudaStreamWaitEvent(s2, evF, 0);

    // stream s2: full edge-sort chain
    zero_kernel<<<(N_NODES + 255) / 256, 256, 0, s2>>>();
    hist_kernel<<<(N_EDGES / 4 + 255) / 256, 256, 0, s2>>>(dst);
    scan_kernel<<<N_SCAN_BLOCKS, SCAN_BLK, 0, s2>>>();
    scatter_kernel<<<(N_EDGES / 4 + 255) / 256, 256, 0, s2>>>(src, dst);
    cudaEventRecord(evJ, s2);

    // stream 0: projection chain
    wtrans_kernel<<<(HF * D_IN + 255) / 256, 256>>>(fc_w);
    gemm_kernel<<<GEMM_GRID, 256, 131072>>>(x, al, ar);

    // join, then aggregation (weights computed inline)
    cudaStreamWaitEvent(0, evJ, 0);
    agg_kernel<<<(N_NODES * 32) / 256, 256>>>(out);
}